// round 17
// baseline (speedup 1.0000x reference)
#include <cuda_runtime.h>
#include <math.h>

// B,H,L,D = 4,8,2048,64 ; FACTOR=5 -> sample_k = n_top = 40
#define Bq    4
#define Hq    8
#define Lq    2048
#define Dq    64
#define BH    (Bq*Hq)
#define SK    40
#define NT    40
#define NP    4            // K slices for k_M2
#define SL    (Lq/NP)      // 512 rows per slice
#define ZSP   4            // l-splits per (p,bh) in k_M2
#define ZL    (Lq/ZSP)     // 512 queries per z
#define LMAX  (ZL*SK)      // staged list worst case (20480)
#define NCH   64           // cumsum chunks
#define CHLEN (Lq/NCH)     // 32
#define NJT   16           // j-tiles (of 128) for fused score+AV
#define JT    (Lq/NJT)     // 128
#define SMEM_M2  (SL*Dq*4 + (ZL+1+3)*4 + LMAX*4)
// sav smem (bytes): qs4 | kt (reused as Vs) | P (topk scratch first) | mtop | dsum | ucnt
#define SAV_QS   0
#define SAV_KT   (SAV_QS + NT*16*16)        // 10240
#define SAV_P    (SAV_KT + JT*65*4)         // 43520 (20480 bytes)
#define SAV_MT   (SAV_P  + NT*JT*4)         // 64000
#define SAV_DS   (SAV_MT + NT*4)            // 64160
#define SAV_UC   (SAV_DS + NT*4)            // 64320
#define SMEM_SAV (SAV_UC + 64)              // 64384

// ---- device scratch (no allocations allowed) ----
__device__ float2 g_part2[NP*BH*Lq];
__device__ float  g_den[BH*NT];
__device__ float  g_part[BH*NJT*NT*Dq];
__device__ float  g_csum[BH*NCH*Dq];
__device__ int    g_ctr2[BH];          // k_sav tail-election counters

// ---------------------------------------------------------------------------
// k_M2: inline prep (per-block inverted list from I) + proven dot core +
// csum1 epilogue + (one block) g_den/g_ctr2 per-replay zeroing.
// ---------------------------------------------------------------------------
__global__ void __launch_bounds__(1024) k_M2(const float* __restrict__ Q,
                                             const float* __restrict__ K,
                                             const float* __restrict__ V,
                                             const int* __restrict__ I) {
    extern __shared__ float ks[];
    float4* ks4 = (float4*)ks;
    int* so = (int*)(ks + SL*Dq);          // ZL+1 exclusive offsets
    int* sl = so + (ZL+1+3);               // staged list
    __shared__ int wsum[16];

    int p = blockIdx.x, bh = blockIdx.y, z = blockIdx.z;
    int tid = threadIdx.x, warp = tid >> 5, lane = tid & 31;
    int g = lane >> 3, e = lane & 7;
    int zl0 = z*ZL;

    // stage K slice (independent of prep; overlaps)
    const float4* Ks = (const float4*)(K + ((size_t)bh*Lq + (size_t)p*SL)*Dq);
    for (int i = tid; i < SL*(Dq/4); i += 1024) ks4[i] = Ks[i];

    // ---- inline prep: count -> scan -> fill (threads 0..ZL-1 own queries) ----
    int cnt = 0;
    if (tid < ZL) {
        const int* r = I + (size_t)(zl0 + tid)*SK;
        #pragma unroll
        for (int s = 0; s < SK; ++s) cnt += ((r[s] >> 9) == p);
    }
    int v = cnt;
    #pragma unroll
    for (int o = 1; o < 32; o <<= 1) {
        int t = __shfl_up_sync(0xffffffffu, v, o);
        if (lane >= o) v += t;
    }
    if (lane == 31 && warp < 16) wsum[warp] = v;
    __syncthreads();
    if (warp == 0 && lane < 16) {
        int y = wsum[lane], inc = y;
        #pragma unroll
        for (int o = 1; o < 16; o <<= 1) {
            int t = __shfl_up_sync(0xffffu, inc, o);
            if (lane >= o) inc += t;
        }
        wsum[lane] = inc - y;              // exclusive
    }
    __syncthreads();
    if (tid < ZL) {
        int excl = v - cnt + wsum[warp];
        so[tid] = excl;
        if (tid == ZL-1) so[ZL] = excl + cnt;
        const int* r = I + (size_t)(zl0 + tid)*SK;
        int o = excl;
        #pragma unroll
        for (int s = 0; s < SK; ++s) {
            int jj = r[s];
            if ((jj >> 9) == p) sl[o++] = jj & (SL-1);
        }
    }
    __syncthreads();

    // ---- dot core (proven R14 config) ----
    const float4* Q4 = (const float4*)Q;
    int l0 = zl0 + warp;
    #pragma unroll 1
    for (int i = 0; i < 16; i += 2) {
        int la = l0 + 32*i, lb = la + 32;
        int lla = warp + 32*i, llb = lla + 32;
        int a0 = so[lla], a1 = so[lla+1];
        int b0 = so[llb], b1 = so[llb+1];
        size_t qra = ((size_t)bh*Lq + la)*16;
        size_t qrb = ((size_t)bh*Lq + lb)*16;
        float4 qa0 = Q4[qra + e], qa1 = Q4[qra + e + 8];
        float4 qb0 = Q4[qrb + e], qb1 = Q4[qrb + e + 8];
        float mx0 = -INFINITY, sm0 = 0.f, mx1 = -INFINITY, sm1 = 0.f;
        int c0 = a0, c1 = b0;
        while (c0 < a1 || c1 < b1) {
            float pr0 = 0.f, pr1 = 0.f;
            bool v0 = false, v1 = false;
            if (c0 < a1) {
                int idx = c0 + g; v0 = idx < a1;
                int j = sl[v0 ? idx : a0];
                const float4* kb = ks4 + (j << 4);
                float4 x = kb[e], y = kb[e + 8];
                pr0 = qa0.x*x.x + qa0.y*x.y + qa0.z*x.z + qa0.w*x.w
                    + qa1.x*y.x + qa1.y*y.y + qa1.z*y.z + qa1.w*y.w;
            }
            if (c1 < b1) {
                int idx = c1 + g; v1 = idx < b1;
                int j = sl[v1 ? idx : b0];
                const float4* kb = ks4 + (j << 4);
                float4 x = kb[e], y = kb[e + 8];
                pr1 = qb0.x*x.x + qb0.y*x.y + qb0.z*x.z + qb0.w*x.w
                    + qb1.x*y.x + qb1.y*y.y + qb1.z*y.z + qb1.w*y.w;
            }
            pr0 += __shfl_xor_sync(0xffffffffu, pr0, 1);
            pr1 += __shfl_xor_sync(0xffffffffu, pr1, 1);
            pr0 += __shfl_xor_sync(0xffffffffu, pr0, 2);
            pr1 += __shfl_xor_sync(0xffffffffu, pr1, 2);
            pr0 += __shfl_xor_sync(0xffffffffu, pr0, 4);
            pr1 += __shfl_xor_sync(0xffffffffu, pr1, 4);
            if (v0) { mx0 = fmaxf(mx0, pr0); sm0 += pr0; }
            if (v1) { mx1 = fmaxf(mx1, pr1); sm1 += pr1; }
            c0 += 4; c1 += 4;
        }
        mx0 = fmaxf(mx0, __shfl_xor_sync(0xffffffffu, mx0, 8));
        mx0 = fmaxf(mx0, __shfl_xor_sync(0xffffffffu, mx0, 16));
        sm0 += __shfl_xor_sync(0xffffffffu, sm0, 8);
        sm0 += __shfl_xor_sync(0xffffffffu, sm0, 16);
        mx1 = fmaxf(mx1, __shfl_xor_sync(0xffffffffu, mx1, 8));
        mx1 = fmaxf(mx1, __shfl_xor_sync(0xffffffffu, mx1, 16));
        sm1 += __shfl_xor_sync(0xffffffffu, sm1, 8);
        sm1 += __shfl_xor_sync(0xffffffffu, sm1, 16);
        if (lane == 0) {
            g_part2[((size_t)p*BH + bh)*Lq + la] = make_float2(mx0, sm0);
            g_part2[((size_t)p*BH + bh)*Lq + lb] = make_float2(mx1, sm1);
        }
    }

    // ---- csum1 epilogue: first 128 blocks compute V chunk sums ----
    int mbid = blockIdx.x + NP*blockIdx.y + NP*BH*blockIdx.z;
    if (mbid < (NCH*BH)/16) {
        int gcid = mbid*16 + (tid >> 6);
        int d = tid & 63;
        int cbh = gcid >> 6, ch = gcid & (NCH-1);
        const float* v = V + ((size_t)cbh*Lq + ch*CHLEN)*Dq + d;
        float a = 0.f;
        #pragma unroll
        for (int l = 0; l < CHLEN; l += 4) {
            float x0 = v[(size_t)l*Dq],     x1 = v[(size_t)(l+1)*Dq];
            float x2 = v[(size_t)(l+2)*Dq], x3 = v[(size_t)(l+3)*Dq];
            a += (x0+x1) + (x2+x3);
        }
        g_csum[(cbh*NCH + ch)*Dq + d] = a;
    } else if (mbid == (NCH*BH)/16) {
        // per-replay zeroing for k_sav's global accumulators (stream-ordered)
        for (int i = tid; i < BH*NT; i += 1024) g_den[i] = 0.f;
        if (tid < BH) g_ctr2[tid] = 0;
    }
}

// ---------------------------------------------------------------------------
// k_sav: per-block REDUNDANT top-40 radix select (deterministic; scratch in
// the dead P buffer), then fused score+exp+AV + cumsum epilogue + fix tail.
// ---------------------------------------------------------------------------
__global__ void __launch_bounds__(256, 3) k_sav(const float* __restrict__ Q,
                                                const float* __restrict__ K,
                                                const float* __restrict__ V,
                                                float* __restrict__ O) {
    extern __shared__ char sm_raw[];
    float4* qs4  = (float4*)(sm_raw + SAV_QS);
    float*  kt   = (float*) (sm_raw + SAV_KT);   // K tile, then V tile
    float*  P    = (float*) (sm_raw + SAV_P);
    int*    mtop = (int*)   (sm_raw + SAV_MT);
    float*  dsum = (float*) (sm_raw + SAV_DS);
    int*    puc  = (int*)   (sm_raw + SAV_UC);

    int jtx = blockIdx.x, bh = blockIdx.y;
    int jt0 = jtx * JT;
    int tid = threadIdx.x, lane = tid & 31, wwid = tid >> 5;
    int j = tid & (JT-1), half = tid >> 7;

    // ---- Phase 0: top-40 select for this bh (scratch = P buffer) ----
    unsigned* keys = (unsigned*)(sm_raw + SAV_P);            // 8KB
    int*      tie  = (int*)(sm_raw + SAV_P + Lq*4);          // 8KB
    __shared__ int hist[256];
    __shared__ int wsc[8];
    __shared__ int tops[NT];
    __shared__ int s_d, s_acc, s_ngt, s_ntie;

    for (int i = tid; i < Lq; i += 256) {
        float mx = -INFINITY, sm = 0.f;
        #pragma unroll
        for (int pp = 0; pp < NP; ++pp) {
            float2 v = g_part2[((size_t)pp*BH + bh)*Lq + i];
            mx = fmaxf(mx, v.x); sm += v.y;
        }
        float m = mx - sm * (1.0f/(float)Lq);
        unsigned u = __float_as_uint(m);
        keys[i] = (u & 0x80000000u) ? ~u : (u | 0x80000000u);
    }
    if (tid == 0) { s_ngt = 0; s_ntie = 0; }
    __syncthreads();

    unsigned prefix = 0; int kk = NT;
    #pragma unroll
    for (int level = 3; level >= 0; --level) {
        int sh = level*8;
        hist[tid] = 0;
        __syncthreads();
        unsigned maskAbove = (level==3) ? 0u : (0xFFFFFFFFu << (sh+8));
        for (int i = tid; i < Lq; i += 256) {
            unsigned key = keys[i];
            if ((key & maskAbove) == prefix)
                atomicAdd(&hist[(key >> sh) & 255], 1);
        }
        __syncthreads();
        // parallel digit pick: reversed inclusive scan over hist
        int hv = hist[255 - tid];
        int x = hv;
        #pragma unroll
        for (int o = 1; o < 32; o <<= 1) {
            int t = __shfl_up_sync(0xffffffffu, x, o);
            if (lane >= o) x += t;
        }
        if (lane == 31) wsc[wwid] = x;
        __syncthreads();
        if (wwid == 0 && lane < 8) {
            int y = wsc[lane], inc = y;
            #pragma unroll
            for (int o = 1; o < 8; o <<= 1) {
                int t = __shfl_up_sync(0xffu, inc, o);
                if (lane >= o) inc += t;
            }
            wsc[lane] = inc - y;
        }
        __syncthreads();
        x += wsc[wwid];
        int above = x - hv;                  // # keys with digit > (255-tid)
        if (x >= kk && above < kk) { s_d = 255 - tid; s_acc = above; }
        __syncthreads();
        kk -= s_acc;
        prefix |= ((unsigned)s_d) << sh;
        __syncthreads();
    }
    unsigned T = prefix;

    for (int i = tid; i < Lq; i += 256) {
        unsigned key = keys[i];
        if (key > T)       { int pos = atomicAdd(&s_ngt, 1);  tops[pos] = i; }
        else if (key == T) { int pos = atomicAdd(&s_ntie, 1); tie[pos]  = i; }
    }
    __syncthreads();
    int ngt = s_ngt, ntie = s_ntie;          // kk still needed from ties
    if (tid < 32) {
        for (int t = 0; t < kk; ++t) {
            long long best = 0x7FFFFFFFFFFFFFFFLL;
            for (int i = tid; i < ntie; i += 32) {
                long long c = ((long long)tie[i] << 32) | (unsigned)i;
                if (c < best) best = c;
            }
            #pragma unroll
            for (int o = 16; o; o >>= 1) {
                long long c = __shfl_xor_sync(0xffffffffu, best, o);
                if (c < best) best = c;
            }
            if (tid == 0) {
                int slot = (int)(best & 0xffffffffu);
                tops[ngt + t] = (int)(best >> 32);
                tie[slot] = 0x7FFFFFFF;
            }
            __syncwarp();
        }
    }
    __syncthreads();

    // rank-sort desc by row index -> canonical mtop (atomics order erased)
    if (tid < NT) {
        int me = tops[tid], r = 0;
        #pragma unroll
        for (int jj = 0; jj < NT; ++jj) r += (tops[jj] > me);
        mtop[r] = me;
    }
    if (tid < NT) dsum[tid] = 0.f;
    __syncthreads();
    if (tid == 0) {
        int c = 0;
        while (c < NT && mtop[c] >= jt0) ++c;
        *puc = c;
    }

    // ---- stage Qr + K tile ----
    const float4* Q4 = (const float4*)Q;
    for (int i = tid; i < NT*16; i += 256) {
        int u = i >> 4, d4 = i & 15;
        qs4[i] = Q4[((size_t)bh*Lq + mtop[u])*16 + d4];
    }
    const float4* K4 = (const float4*)K;
    for (int i = tid; i < JT*16; i += 256) {
        int r = i >> 4, c4 = i & 15;
        float4 v = K4[((size_t)bh*Lq + jt0 + r)*16 + c4];
        kt[r*65 + c4*4+0] = v.x; kt[r*65 + c4*4+1] = v.y;
        kt[r*65 + c4*4+2] = v.z; kt[r*65 + c4*4+3] = v.w;
    }
    __syncthreads();
    int ucnt = *puc;

    // extract K row into registers; kt bytes are dead afterwards
    float kr[Dq];
    #pragma unroll
    for (int d = 0; d < Dq; ++d) kr[d] = kt[j*65 + d];
    __syncthreads();                       // everyone done reading kt

    // stage V tile into the former kt bytes (overlaps with phase A compute)
    float* Vs = kt;                        // [JT][Dq] row-major
    float4* Vs4 = (float4*)Vs;
    const float4* V4 = (const float4*)V;
    for (int i = tid; i < JT*16; i += 256)
        Vs4[i] = V4[((size_t)bh*Lq + jt0)*16 + i];

    // ---- Phase A: scores -> exp -> smem P (live u only) ----
    int jg = jt0 + j;
    #pragma unroll 1
    for (int u = half; u < ucnt; u += 2) {
        int m = mtop[u];
        float s = 0.f;
        #pragma unroll
        for (int d4 = 0; d4 < 16; ++d4) {
            float4 qv = qs4[u*16 + d4];
            s += kr[d4*4+0]*qv.x + kr[d4*4+1]*qv.y + kr[d4*4+2]*qv.z + kr[d4*4+3]*qv.w;
        }
        float e = (jg > m) ? 0.f : __expf(s * 0.125f);
        P[u*JT + j] = e;
        float v = e;
        v += __shfl_xor_sync(0xffffffffu, v, 1);
        v += __shfl_xor_sync(0xffffffffu, v, 2);
        v += __shfl_xor_sync(0xffffffffu, v, 4);
        v += __shfl_xor_sync(0xffffffffu, v, 8);
        v += __shfl_xor_sync(0xffffffffu, v, 16);
        if (lane == 0) atomicAdd(&dsum[u], v);
    }
    __syncthreads();                       // P + Vs both ready
    if (tid < NT) atomicAdd(&g_den[bh*NT + tid], dsum[tid]);

    // ---- Phase B: AV partials from smem P + smem Vs ----
    int d = tid & 63, ug = tid >> 6;
    const float4* P4 = (const float4*)P;
    float acc[10];
    #pragma unroll
    for (int k = 0; k < 10; ++k) acc[k] = 0.f;

    #pragma unroll 1
    for (int j4 = 0; j4 < JT/4; ++j4) {
        float v0 = Vs[(j4*4+0)*Dq + d], v1 = Vs[(j4*4+1)*Dq + d];
        float v2 = Vs[(j4*4+2)*Dq + d], v3 = Vs[(j4*4+3)*Dq + d];
        #pragma unroll
        for (int k = 0; k < 10; ++k) {
            int u = ug*10 + k;
            if (u < ucnt) {
                float4 pv = P4[u*(JT/4) + j4];
                acc[k] += pv.x*v0 + pv.y*v1 + pv.z*v2 + pv.w*v3;
            }
        }
    }
    #pragma unroll
    for (int k = 0; k < 10; ++k)
        g_part[(((size_t)bh*NJT + jtx)*NT + ug*10 + k)*Dq + d] = acc[k];

    // ---- Epilogue: cumsum output for one chunk-group (no scatter) ----
    {
        int sbid = jtx + NJT*bh;                 // [0, 512)
        int cbh = sbid >> 4;                     // == bh
        int ch = (sbid & 15)*4 + (tid >> 6);
        int dd = tid & 63;
        float a = 0.f;
        int c = 0;
        for (; c + 4 <= ch; c += 4) {
            float x0 = g_csum[(cbh*NCH + c+0)*Dq + dd];
            float x1 = g_csum[(cbh*NCH + c+1)*Dq + dd];
            float x2 = g_csum[(cbh*NCH + c+2)*Dq + dd];
            float x3 = g_csum[(cbh*NCH + c+3)*Dq + dd];
            a += (x0+x1) + (x2+x3);
        }
        for (; c < ch; ++c) a += g_csum[(cbh*NCH + c)*Dq + dd];

        size_t base = ((size_t)cbh*Lq + ch*CHLEN)*Dq + dd;
        #pragma unroll 4
        for (int l = 0; l < CHLEN; ++l) {
            a += V[base + (size_t)l*Dq];
            O[base + (size_t)l*Dq] = a;
        }
    }

    // ---- tail election: last of the 16 blocks for this bh runs the fix ----
    __shared__ int s_last2;
    if (tid == 0) {
        __threadfence();
        int c = atomicAdd(&g_ctr2[bh], 1);
        s_last2 = (c == NJT - 1);
    }
    __syncthreads();
    if (!s_last2) return;
    __threadfence();                       // acquire g_part/g_den/O writes

    for (int i = tid; i < NT*Dq; i += 256) {
        int u = i >> 6, dd = i & 63;
        int row = mtop[u];
        float acc2 = 0.f;
        #pragma unroll
        for (int js = 0; js < NJT; ++js)
            acc2 += g_part[(((size_t)bh*NJT + js)*NT + u)*Dq + dd];
        O[((size_t)bh*Lq + row)*Dq + dd] = acc2 / g_den[bh*NT + u];
    }
}

extern "C" void kernel_launch(void* const* d_in, const int* in_sizes, int n_in,
                              void* d_out, int out_size) {
    const float* Q = (const float*)d_in[0];
    const float* K = (const float*)d_in[1];
    const float* V = (const float*)d_in[2];
    const int*   I = (const int*)  d_in[3];
    float* O = (float*)d_out;

    cudaFuncSetAttribute(k_M2,  cudaFuncAttributeMaxDynamicSharedMemorySize, SMEM_M2);
    cudaFuncSetAttribute(k_sav, cudaFuncAttributeMaxDynamicSharedMemorySize, SMEM_SAV);

    k_M2  <<<dim3(NP, BH, ZSP), 1024, SMEM_M2>>>(Q, K, V, I);
    k_sav <<<dim3(NJT, BH), 256, SMEM_SAV>>>(Q, K, V, O);
}